// round 14
// baseline (speedup 1.0000x reference)
#include <cuda_runtime.h>
#include <cuda_bf16.h>
#include <cstdint>

#define Bd 8
#define Nd 65536
#define Cd 64
#define Md 64
#define CAP 36
#define Sp 256            // proj splits per batch (4 chunks of 64 n each)
#define PCHUNKS ((Nd / Sp) / 64)
#define SLICE (Bd * Cd * 80)
#define TWOPI 6.283185307179586f

typedef unsigned short ush;

// ---------------- device scratch (no allocation; statically zeroed) --------
__device__ float g_rep_fx[CAP], g_rep_fy[CAP];
__device__ int   g_rep_m[CAP], g_rep_pair[CAP];
__device__ float g_partial[(size_t)Sp * SLICE];          // [split][b][c][80]
__device__ float g_red[(size_t)8 * SLICE];               // [8][b][c][80]
__device__ ush   g_W[(size_t)Bd * Cd * 160];             // [b][c][160]; pads stay 0

// ---------------- helpers ----------------
__device__ __forceinline__ void splitb(float x, ush& h, ush& l) {
    uint32_t u = __float_as_uint(x);
    h = (ush)(u >> 16);                                   // truncation (exact hi)
    __nv_bfloat16 lb = __float2bfloat16(x - __uint_as_float(u & 0xFFFF0000u));
    l = *reinterpret_cast<ush*>(&lb);
}
// hi word of pair: {lo16: trunc16(f0), hi16: trunc16(f1)}
__device__ __forceinline__ uint32_t hi_pair(float f0, float f1) {
    uint32_t r;
    asm("prmt.b32 %0, %1, %2, 0x7632;" : "=r"(r)
        : "r"(__float_as_uint(f0)), "r"(__float_as_uint(f1)));
    return r;
}
// lo word of pair: {lo16: bf16(f0-hi0), hi16: bf16(f1-hi1)}
__device__ __forceinline__ uint32_t lo_pair(float f0, float f1) {
    float l0 = f0 - __uint_as_float(__float_as_uint(f0) & 0xFFFF0000u);
    float l1 = f1 - __uint_as_float(__float_as_uint(f1) & 0xFFFF0000u);
    uint32_t r;
    asm("cvt.rn.bf16x2.f32 %0, %1, %2;" : "=r"(r) : "f"(l1), "f"(l0));
    return r;
}
__device__ __forceinline__ void trig_of2(float cx, float cy, float fx, float fy,
                                         float& s, float& c) {
    float t = cx * fx + cy * fy;                          // integer freqs
    float ph = TWOPI * (t - rintf(t));                    // exact reduce to [-pi,pi]
    __sincosf(ph, &s, &c);
}
// D(16x8,f32) += A(16x16 row,bf16) * B(16x8 col,bf16)
__device__ __forceinline__ void hmma(float* d, const uint32_t* a, const uint32_t* b) {
    asm volatile(
        "mma.sync.aligned.m16n8k16.row.col.f32.bf16.bf16.f32 "
        "{%0,%1,%2,%3},{%4,%5,%6,%7},{%8,%9},{%0,%1,%2,%3};"
        : "+f"(d[0]), "+f"(d[1]), "+f"(d[2]), "+f"(d[3])
        : "r"(a[0]), "r"(a[1]), "r"(a[2]), "r"(a[3]), "r"(b[0]), "r"(b[1]));
}
__device__ __forceinline__ void ldsm4(uint32_t* r, uint32_t a) {
    asm volatile("ldmatrix.sync.aligned.m8n8.x4.shared.b16 {%0,%1,%2,%3}, [%4];"
        : "=r"(r[0]), "=r"(r[1]), "=r"(r[2]), "=r"(r[3]) : "r"(a));
}
__device__ __forceinline__ void ldsm2(uint32_t* r, uint32_t a) {
    asm volatile("ldmatrix.sync.aligned.m8n8.x2.shared.b16 {%0,%1}, [%2];"
        : "=r"(r[0]), "=r"(r[1]) : "r"(a));
}

// ---------------------------------------------------------------------------
// K0: conjugate-pair discovery (parallel; deterministic rep order)
// ---------------------------------------------------------------------------
__global__ void setup_kernel(const float* __restrict__ freqs) {
    __shared__ float sfx[Md], sfy[Md];
    __shared__ int sp[Md];
    const int m = threadIdx.x;                 // 64 threads
    const float fx = freqs[2 * m], fy = freqs[2 * m + 1];
    sfx[m] = fx; sfy[m] = fy;
    __syncthreads();
    int p = -1;
    for (int q = 0; q < Md; q++)
        if (q != m && sfx[q] == -fx && sfy[q] == -fy) { p = q; break; }
    sp[m] = p;
    __syncthreads();
    if (m == 0) {
        int cnt = 0;
        for (int mm = 0; mm < Md && cnt < CAP; mm++) {
            const int pp = sp[mm];
            if (pp >= 0 && pp < mm) continue;  // covered by an earlier rep
            g_rep_m[cnt] = mm; g_rep_pair[cnt] = pp;
            g_rep_fx[cnt] = sfx[mm]; g_rep_fy[cnt] = sfy[mm]; cnt++;
        }
        for (int j = cnt; j < CAP; j++) {
            g_rep_m[j] = -1; g_rep_pair[j] = -1;
            g_rep_fx[j] = 0.f; g_rep_fy[j] = 0.f;
        }
    }
}

// ---------------------------------------------------------------------------
// K1 proj: D[c(64)][j2(80)] += X[c][k] * T[j2][k] over n, bf16 hi/lo.
// Direct gmem->bf16 build; LDSM fragment loads (4 LDSM / kstep).
// smem: Xw[64 c][68 words] | Tw[80 j2][68 words]   (hi words 0-31, lo 32-63)
// ---------------------------------------------------------------------------
#define PSTRW 68
#define PROJ_SMEM ((64 + 80) * PSTRW * 4)

__global__ __launch_bounds__(256, 4) void proj_kernel(
    const float* __restrict__ inputs, const float* __restrict__ coords)
{
    extern __shared__ __align__(16) uint32_t smw[];
    uint32_t* Xw = smw;                        // [64][68]
    uint32_t* Tw = smw + 64 * PSTRW;           // [80][68]

    const int tid = threadIdx.x, wid = tid >> 5, lane = tid & 31;
    const int g = lane >> 2, tq = lane & 3;
    const int split = blockIdx.x, b = blockIdx.y;

    // zero T pad rows 72-79 once (read by MMA, never written)
    for (int i = tid; i < 8 * PSTRW; i += 256) Tw[72 * PSTRW + i] = 0;

    const int mt = wid >> 1;                   // c tile: c0 = mt*16
    const int nb = (wid & 1) * 5;              // j2 tiles nb..nb+4

    // LDSM lane addresses (bytes, shared space)
    const uint32_t sX = (uint32_t)__cvta_generic_to_shared(Xw);
    const uint32_t sT = (uint32_t)__cvta_generic_to_shared(Tw);
    const uint32_t aA = sX + (((mt * 16 + (lane & 15)) * PSTRW) + (lane >> 4) * 4) * 4;
    const int br = lane & 7, kq = (lane >> 3) & 1, ts = lane >> 4;
    const uint32_t aB0 = sT + ((((nb + ts) * 8 + br) * PSTRW) + kq * 4) * 4;
    const uint32_t aB1 = sT + ((((nb + 2 + ts) * 8 + br) * PSTRW) + kq * 4) * 4;
    const uint32_t aB2 = sT + ((((nb + 4) * 8 + br) * PSTRW) + kq * 4) * 4;

    float acc[5][4];
    #pragma unroll
    for (int u = 0; u < 5; u++)
        #pragma unroll
        for (int v = 0; v < 4; v++) acc[u][v] = 0.f;

    const int nbase = split * (Nd / Sp);
    const int npl = 4 * wid + tq;              // this lane's n-pair (0..31)

    for (int t = 0; t < PCHUNKS; t++) {
        const int n0 = nbase + t * 64;
        __syncthreads();                       // tiles free (prev MMA done)

        // ---- X build: direct LDG -> pairwise bf16 -> CF STS ----
        {
            const float* xrow = inputs + ((size_t)b * Nd + n0) * Cd;
            const int r0 = 2 * npl;
            #pragma unroll
            for (int ic = 0; ic < 8; ic++) {
                const int c = g + 8 * ic;
                const float f0 = xrow[(size_t)r0 * Cd + c];
                const float f1 = xrow[(size_t)(r0 + 1) * Cd + c];
                Xw[c * PSTRW + npl]      = hi_pair(f0, f1);
                Xw[c * PSTRW + 32 + npl] = lo_pair(f0, f1);
            }
        }
        // ---- T build: 1152 (j, n-pair) items, pairwise conversion ----
        {
            const float* cbase = coords + ((size_t)b * Nd + n0) * 2;
            for (int e = tid; e < 1152; e += 256) {
                const int j = e >> 5, w = e & 31;
                const float4 cc = *(const float4*)(cbase + 4 * w);
                const float fx = g_rep_fx[j], fy = g_rep_fy[j];
                float s0, c0, s1, c1;
                trig_of2(cc.x, cc.y, fx, fy, s0, c0);
                trig_of2(cc.z, cc.w, fx, fy, s1, c1);
                uint32_t* r = Tw + j * PSTRW;
                r[w]      = hi_pair(c0, c1);
                r[32 + w] = lo_pair(c0, c1);
                r += 36 * PSTRW;
                r[w]      = hi_pair(s0, s1);
                r[32 + w] = lo_pair(s0, s1);
            }
        }
        __syncthreads();

        // ---- MMA: 12 ksteps, LDSM fragments ----
        #pragma unroll
        for (int gr = 0; gr < 3; gr++) {
            const int kwAb = (gr == 1) ? 32 : 0;     // X lo for group 1
            const int kwBb = (gr == 2) ? 32 : 0;     // T lo for group 2
            #pragma unroll
            for (int s = 0; s < 4; s++) {
                const uint32_t oA = (uint32_t)(kwAb + 8 * s) * 4;
                const uint32_t oB = (uint32_t)(kwBb + 8 * s) * 4;
                uint32_t a[4], b01[4], b23[4], b4[2];
                ldsm4(a, aA + oA);
                ldsm4(b01, aB0 + oB);
                ldsm4(b23, aB1 + oB);
                ldsm2(b4,  aB2 + oB);
                hmma(acc[0], a, b01);
                hmma(acc[1], a, b01 + 2);
                hmma(acc[2], a, b23);
                hmma(acc[3], a, b23 + 2);
                hmma(acc[4], a, b4);
            }
        }
    }

    // epilogue: D[c][j2] -> g_partial[split][b][c][80]
    float* dst = g_partial + (((size_t)split * Bd + b) * Cd) * 80;
    #pragma unroll
    for (int u = 0; u < 5; u++) {
        const int j = (nb + u) * 8 + 2 * tq;
        const int c0 = mt * 16 + g;
        *(float2*)&dst[(size_t)c0 * 80 + j]       = make_float2(acc[u][0], acc[u][1]);
        *(float2*)&dst[(size_t)(c0 + 8) * 80 + j] = make_float2(acc[u][2], acc[u][3]);
    }
}

// ---------------------------------------------------------------------------
// K2a: parallel reduce Sp slices -> 8 (coalesced; deterministic grouping)
// ---------------------------------------------------------------------------
__global__ __launch_bounds__(256) void reduce_kernel() {
    const int idx = blockIdx.x * 256 + threadIdx.x;       // over 8*SLICE
    const int r8 = idx / SLICE;
    const int rem = idx - r8 * SLICE;
    const float* p = g_partial + (size_t)r8 * (Sp / 8) * SLICE + rem;
    float s = 0.f;
    #pragma unroll 8
    for (int i = 0; i < Sp / 8; i++) s += p[(size_t)i * SLICE];
    g_red[idx] = s;
}

// ---------------------------------------------------------------------------
// K2b mix: reduce 8 slices, 1/N + weight + conj fold, emit bf16 hi/lo W
// ---------------------------------------------------------------------------
__global__ __launch_bounds__(256) void mix_kernel(
    const float* __restrict__ wre, const float* __restrict__ wim)
{
    const int idx = blockIdx.x * 256 + threadIdx.x;       // Bd*64*36
    const int b = idx / (Cd * CAP);
    const int rem = idx - b * (Cd * CAP);
    const int c = rem / CAP, j = rem - c * CAP;
    const int m = g_rep_m[j];
    if (m < 0) return;

    float cr = 0.f, si = 0.f;
    const float* p = g_red + ((size_t)b * Cd + c) * 80;
    #pragma unroll
    for (int s = 0; s < 8; s++) {
        cr += p[(size_t)s * SLICE + j];
        si += p[(size_t)s * SLICE + 36 + j];
    }
    const float ci = -si, inv = 1.0f / (float)Nd;
    const float wr = wre[m * Cd + c], wi = wim[m * Cd + c];
    float A2 =  (cr * wr - ci * wi) * inv;
    float B2 = -(cr * wi + ci * wr) * inv;
    const int pp = g_rep_pair[j];
    if (pp >= 0) {
        const float wrp = wre[pp * Cd + c], wip = wim[pp * Cd + c];
        A2 += ( cr * wrp + ci * wip) * inv;
        B2 -= (-cr * wip + ci * wrp) * inv;
    }
    ush ah, al, bh, bl;
    splitb(A2, ah, al); splitb(B2, bh, bl);
    ush* W = g_W + ((size_t)b * Cd + c) * 160;
    W[j] = ah; W[36 + j] = bh; W[80 + j] = al; W[116 + j] = bl;
}

// ---------------------------------------------------------------------------
// K3 recon: D[n(128)][c(64)] = T[n][k] * W[c][k]
// warp = (n32-tile, c32-half); LDSM fragments (4 LDSM / kstep).
// smem: Ts[128][168]h | Ws[64][168]h
// ---------------------------------------------------------------------------
#define RSTR 168
#define RSTRW 84
#define WS_OFF (128 * RSTR)
#define RECON_SMEM ((128 + 64) * RSTR * 2)

__global__ __launch_bounds__(256, 2) void recon_kernel(
    const float* __restrict__ coords, float* __restrict__ out)
{
    extern __shared__ __align__(16) ush sm[];
    ush* Ws = sm + WS_OFF;
    uint32_t* Twr = (uint32_t*)sm;
    uint32_t* Wwr = (uint32_t*)Ws;

    const int tid = threadIdx.x, wid = tid >> 5, lane = tid & 31;
    const int g = lane >> 2, tq = lane & 3;
    const int b = blockIdx.y, n0 = blockIdx.x * 128;

    // zero Ts pad words: hi-pad 36..39 (halves 72..79) AND lo-pad 76..79
    // (halves 152..159) — both are read by the kstep loops.
    if (tid < 128) {
        uint32_t* r = Twr + tid * RSTRW;
        r[36] = 0; r[37] = 0; r[38] = 0; r[39] = 0;
        r[76] = 0; r[77] = 0; r[78] = 0; r[79] = 0;
    }
    // W tile: 64 rows x 20 uint4 (g_W pads are statically zero)
    for (int v = tid; v < 1280; v += 256) {
        const int c = v / 20, q2 = v - c * 20;
        const uint4 w = *(const uint4*)(g_W + ((size_t)b * Cd + c) * 160 + q2 * 8);
        *(uint4*)&Ws[c * RSTR + q2 * 8] = w;
    }
    // T tile: packed STS.32, jw-major: 128 n x 18 mode-pair words
    {
        const float2* cbase = ((const float2*)coords) + (size_t)b * Nd + n0;
        #pragma unroll
        for (int i = 0; i < 9; i++) {
            const int e = tid + 256 * i;              // 0..2303
            const int n = e / 18, jw = e - n * 18;
            const float2 cc = cbase[n];
            const int j0 = 2 * jw, j1 = j0 + 1;
            float s0, c0, s1, c1;
            trig_of2(cc.x, cc.y, g_rep_fx[j0], g_rep_fy[j0], s0, c0);
            trig_of2(cc.x, cc.y, g_rep_fx[j1], g_rep_fy[j1], s1, c1);
            uint32_t* r = Twr + n * RSTRW;
            r[jw]      = hi_pair(c0, c1);
            r[18 + jw] = hi_pair(s0, s1);
            r[40 + jw] = lo_pair(c0, c1);
            r[58 + jw] = lo_pair(s0, s1);
        }
    }
    __syncthreads();

    const int nt = wid & 3;          // n32 tile: rows nt*32 .. +31
    const int ch = wid >> 2;         // c32 half: col tiles ch*4 .. ch*4+3

    // LDSM lane addresses
    const uint32_t sT = (uint32_t)__cvta_generic_to_shared(Twr);
    const uint32_t sW2 = (uint32_t)__cvta_generic_to_shared(Wwr);
    const uint32_t aA0 = sT + (((nt * 32 + (lane & 15)) * RSTRW) + (lane >> 4) * 4) * 4;
    const uint32_t aA1 = aA0 + 16 * RSTRW * 4;
    const int br = lane & 7, kq = (lane >> 3) & 1, ts = lane >> 4;
    const uint32_t aB0 = sW2 + ((((ch * 4 + ts) * 8 + br) * RSTRW) + kq * 4) * 4;
    const uint32_t aB1 = sW2 + ((((ch * 4 + 2 + ts) * 8 + br) * RSTRW) + kq * 4) * 4;

    float acc[2][4][4];
    #pragma unroll
    for (int t = 0; t < 2; t++)
        #pragma unroll
        for (int u = 0; u < 4; u++)
            #pragma unroll
            for (int v = 0; v < 4; v++) acc[t][u][v] = 0.f;

    // 15 ksteps = 3 groups x 5; LDSM fragments
    #pragma unroll
    for (int s = 0; s < 15; s++) {
        const int gr = s / 5, s5 = s - gr * 5;
        const uint32_t oA = (uint32_t)(((gr == 1) ? 40 : 0) + 8 * s5) * 4;  // T lo g1
        const uint32_t oB = (uint32_t)(((gr == 2) ? 40 : 0) + 8 * s5) * 4;  // W lo g2
        uint32_t a0[4], a1[4], b01[4], b23[4];
        ldsm4(a0, aA0 + oA);
        ldsm4(a1, aA1 + oA);
        ldsm4(b01, aB0 + oB);
        ldsm4(b23, aB1 + oB);
        hmma(acc[0][0], a0, b01); hmma(acc[0][1], a0, b01 + 2);
        hmma(acc[0][2], a0, b23); hmma(acc[0][3], a0, b23 + 2);
        hmma(acc[1][0], a1, b01); hmma(acc[1][1], a1, b01 + 2);
        hmma(acc[1][2], a1, b23); hmma(acc[1][3], a1, b23 + 2);
    }

    // epilogue: D[n][c] -> out
    #pragma unroll
    for (int tt = 0; tt < 2; tt++) {
        const int r0 = nt * 32 + tt * 16 + g;
        float* o0 = out + ((size_t)b * Nd + n0 + r0) * Cd;
        float* o1 = o0 + 8 * Cd;
        #pragma unroll
        for (int u = 0; u < 4; u++) {
            const int c = (ch * 4 + u) * 8 + 2 * tq;
            *(float2*)&o0[c] = make_float2(acc[tt][u][0], acc[tt][u][1]);
            *(float2*)&o1[c] = make_float2(acc[tt][u][2], acc[tt][u][3]);
        }
    }
}

// ---------------------------------------------------------------------------
extern "C" void kernel_launch(void* const* d_in, const int* in_sizes, int n_in,
                              void* d_out, int out_size)
{
    const float* inputs = (const float*)d_in[0];
    const float* coords = (const float*)d_in[1];
    const float* wre    = (const float*)d_in[2];
    const float* wim    = (const float*)d_in[3];
    const float* freqs  = (const float*)d_in[4];
    float* out = (float*)d_out;

    cudaFuncSetAttribute(proj_kernel,  cudaFuncAttributeMaxDynamicSharedMemorySize, PROJ_SMEM);
    cudaFuncSetAttribute(recon_kernel, cudaFuncAttributeMaxDynamicSharedMemorySize, RECON_SMEM);

    setup_kernel<<<1, 64>>>(freqs);
    proj_kernel<<<dim3(Sp, Bd), 256, PROJ_SMEM>>>(inputs, coords);
    reduce_kernel<<<(8 * SLICE) / 256, 256>>>();
    mix_kernel<<<(Bd * Cd * CAP) / 256, 256>>>(wre, wim);
    recon_kernel<<<dim3(Nd / 128, Bd), 256, RECON_SMEM>>>(coords, out);
}

// round 16
// speedup vs baseline: 1.0020x; 1.0020x over previous
#include <cuda_runtime.h>
#include <cuda_bf16.h>
#include <cstdint>

#define Bd 8
#define Nd 65536
#define Cd 64
#define Md 64
#define CAP 36
#define Sp 256            // proj splits per batch (4 chunks of 64 n each)
#define PCHUNKS ((Nd / Sp) / 64)
#define SLICE (Bd * Cd * 80)
#define TWOPI 6.283185307179586f

typedef unsigned short ush;

// ---------------- device scratch (no allocation; statically zeroed) --------
__device__ float g_rep_fx[CAP], g_rep_fy[CAP];
__device__ int   g_rep_m[CAP], g_rep_pair[CAP];
__device__ float g_partial[(size_t)Sp * SLICE];          // [split][b][c][80]
__device__ float g_red[(size_t)8 * SLICE];               // [8][b][c][80]
__device__ ush   g_W[(size_t)Bd * Cd * 160];             // [b][c][160]; pads stay 0

// ---------------- helpers ----------------
__device__ __forceinline__ void splitb(float x, ush& h, ush& l) {
    uint32_t u = __float_as_uint(x);
    h = (ush)(u >> 16);                                   // truncation (exact hi)
    __nv_bfloat16 lb = __float2bfloat16(x - __uint_as_float(u & 0xFFFF0000u));
    l = *reinterpret_cast<ush*>(&lb);
}
// hi word of pair: {lo16: trunc16(f0), hi16: trunc16(f1)}
__device__ __forceinline__ uint32_t hi_pair(float f0, float f1) {
    uint32_t r;
    asm("prmt.b32 %0, %1, %2, 0x7632;" : "=r"(r)
        : "r"(__float_as_uint(f0)), "r"(__float_as_uint(f1)));
    return r;
}
// lo word of pair: {lo16: bf16(f0-hi0), hi16: bf16(f1-hi1)}
__device__ __forceinline__ uint32_t lo_pair(float f0, float f1) {
    float l0 = f0 - __uint_as_float(__float_as_uint(f0) & 0xFFFF0000u);
    float l1 = f1 - __uint_as_float(__float_as_uint(f1) & 0xFFFF0000u);
    uint32_t r;
    asm("cvt.rn.bf16x2.f32 %0, %1, %2;" : "=r"(r) : "f"(l1), "f"(l0));
    return r;
}
__device__ __forceinline__ void trig_of2(float cx, float cy, float fx, float fy,
                                         float& s, float& c) {
    float t = cx * fx + cy * fy;                          // integer freqs
    float ph = TWOPI * (t - rintf(t));                    // exact reduce to [-pi,pi]
    __sincosf(ph, &s, &c);
}
// D(16x8,f32) += A(16x16 row,bf16) * B(16x8 col,bf16)
__device__ __forceinline__ void hmma(float* d, const uint32_t* a, const uint32_t* b) {
    asm volatile(
        "mma.sync.aligned.m16n8k16.row.col.f32.bf16.bf16.f32 "
        "{%0,%1,%2,%3},{%4,%5,%6,%7},{%8,%9},{%0,%1,%2,%3};"
        : "+f"(d[0]), "+f"(d[1]), "+f"(d[2]), "+f"(d[3])
        : "r"(a[0]), "r"(a[1]), "r"(a[2]), "r"(a[3]), "r"(b[0]), "r"(b[1]));
}

// ---------------------------------------------------------------------------
// K0: conjugate-pair discovery (parallel; deterministic rep order)
// ---------------------------------------------------------------------------
__global__ void setup_kernel(const float* __restrict__ freqs) {
    __shared__ float sfx[Md], sfy[Md];
    __shared__ int sp[Md];
    const int m = threadIdx.x;                 // 64 threads
    const float fx = freqs[2 * m], fy = freqs[2 * m + 1];
    sfx[m] = fx; sfy[m] = fy;
    __syncthreads();
    int p = -1;
    for (int q = 0; q < Md; q++)
        if (q != m && sfx[q] == -fx && sfy[q] == -fy) { p = q; break; }
    sp[m] = p;
    __syncthreads();
    if (m == 0) {
        int cnt = 0;
        for (int mm = 0; mm < Md && cnt < CAP; mm++) {
            const int pp = sp[mm];
            if (pp >= 0 && pp < mm) continue;  // covered by an earlier rep
            g_rep_m[cnt] = mm; g_rep_pair[cnt] = pp;
            g_rep_fx[cnt] = sfx[mm]; g_rep_fy[cnt] = sfy[mm]; cnt++;
        }
        for (int j = cnt; j < CAP; j++) {
            g_rep_m[j] = -1; g_rep_pair[j] = -1;
            g_rep_fx[j] = 0.f; g_rep_fy[j] = 0.f;
        }
    }
}

// ---------------------------------------------------------------------------
// K1 proj: D[c(64)][j2(80)] += X[c][k] * T[j2][k] over n, bf16 hi/lo.
// Direct gmem->bf16 build (no float staging); plain LDS fragment loads.
// smem: Xw[64 c][68 words] | Tw[80 j2][68 words]   (hi words 0-31, lo 32-63)
// ---------------------------------------------------------------------------
#define PSTRW 68
#define PROJ_SMEM ((64 + 80) * PSTRW * 4)

__global__ __launch_bounds__(256, 4) void proj_kernel(
    const float* __restrict__ inputs, const float* __restrict__ coords)
{
    extern __shared__ __align__(16) uint32_t smw[];
    uint32_t* Xw = smw;                        // [64][68]
    uint32_t* Tw = smw + 64 * PSTRW;           // [80][68]

    const int tid = threadIdx.x, wid = tid >> 5, lane = tid & 31;
    const int g = lane >> 2, tq = lane & 3;
    const int split = blockIdx.x, b = blockIdx.y;

    // zero T pad rows 72-79 once (read by MMA, never written)
    for (int i = tid; i < 8 * PSTRW; i += 256) Tw[72 * PSTRW + i] = 0;

    const int mt = wid >> 1;                   // c tile: c0 = mt*16
    const int nb = (wid & 1) * 5;              // j2 tiles nb..nb+4

    float acc[5][4];
    #pragma unroll
    for (int u = 0; u < 5; u++)
        #pragma unroll
        for (int v = 0; v < 4; v++) acc[u][v] = 0.f;

    const int nbase = split * (Nd / Sp);
    const int npl = 4 * wid + tq;              // this lane's n-pair (0..31)

    for (int t = 0; t < PCHUNKS; t++) {
        const int n0 = nbase + t * 64;
        __syncthreads();                       // tiles free (prev MMA done)

        // ---- X build: direct LDG -> pairwise bf16 -> CF STS ----
        {
            const float* xrow = inputs + ((size_t)b * Nd + n0) * Cd;
            const int r0 = 2 * npl;
            #pragma unroll
            for (int ic = 0; ic < 8; ic++) {
                const int c = g + 8 * ic;
                const float f0 = xrow[(size_t)r0 * Cd + c];
                const float f1 = xrow[(size_t)(r0 + 1) * Cd + c];
                Xw[c * PSTRW + npl]      = hi_pair(f0, f1);
                Xw[c * PSTRW + 32 + npl] = lo_pair(f0, f1);
            }
        }
        // ---- T build: 1152 (j, n-pair) items, pairwise conversion ----
        {
            const float* cbase = coords + ((size_t)b * Nd + n0) * 2;
            for (int e = tid; e < 1152; e += 256) {
                const int j = e >> 5, w = e & 31;
                const float4 cc = *(const float4*)(cbase + 4 * w);
                const float fx = g_rep_fx[j], fy = g_rep_fy[j];
                float s0, c0, s1, c1;
                trig_of2(cc.x, cc.y, fx, fy, s0, c0);
                trig_of2(cc.z, cc.w, fx, fy, s1, c1);
                uint32_t* r = Tw + j * PSTRW;
                r[w]      = hi_pair(c0, c1);
                r[32 + w] = lo_pair(c0, c1);
                r += 36 * PSTRW;
                r[w]      = hi_pair(s0, s1);
                r[32 + w] = lo_pair(s0, s1);
            }
        }
        __syncthreads();

        // ---- MMA: 12 ksteps = 3 product groups x 4 ----
        #pragma unroll
        for (int gr = 0; gr < 3; gr++) {
            const int kwAb = (gr == 1) ? 32 : 0;     // X lo for group 1
            const int kwBb = (gr == 2) ? 32 : 0;     // T lo for group 2
            #pragma unroll
            for (int s = 0; s < 4; s++) {
                const int kwA = kwAb + 8 * s, kwB = kwBb + 8 * s;
                uint32_t a[4];
                const int ra = (mt * 16 + g) * PSTRW + kwA + tq;
                a[0] = Xw[ra];              a[1] = Xw[ra + 8 * PSTRW];
                a[2] = Xw[ra + 4];          a[3] = Xw[ra + 8 * PSTRW + 4];
                #pragma unroll
                for (int u = 0; u < 5; u++) {
                    uint32_t bb[2];
                    const int rb = ((nb + u) * 8 + g) * PSTRW + kwB + tq;
                    bb[0] = Tw[rb]; bb[1] = Tw[rb + 4];
                    hmma(acc[u], a, bb);
                }
            }
        }
    }

    // epilogue: D[c][j2] -> g_partial[split][b][c][80]
    float* dst = g_partial + (((size_t)split * Bd + b) * Cd) * 80;
    #pragma unroll
    for (int u = 0; u < 5; u++) {
        const int j = (nb + u) * 8 + 2 * tq;
        const int c0 = mt * 16 + g;
        *(float2*)&dst[(size_t)c0 * 80 + j]       = make_float2(acc[u][0], acc[u][1]);
        *(float2*)&dst[(size_t)(c0 + 8) * 80 + j] = make_float2(acc[u][2], acc[u][3]);
    }
}

// ---------------------------------------------------------------------------
// K2a: parallel reduce Sp slices -> 8 (coalesced; deterministic grouping)
// ---------------------------------------------------------------------------
__global__ __launch_bounds__(256) void reduce_kernel() {
    const int idx = blockIdx.x * 256 + threadIdx.x;       // over 8*SLICE
    const int r8 = idx / SLICE;
    const int rem = idx - r8 * SLICE;
    const float* p = g_partial + (size_t)r8 * (Sp / 8) * SLICE + rem;
    float s = 0.f;
    #pragma unroll 8
    for (int i = 0; i < Sp / 8; i++) s += p[(size_t)i * SLICE];
    g_red[idx] = s;
}

// ---------------------------------------------------------------------------
// K2b mix: reduce 8 slices, 1/N + weight + conj fold, emit bf16 hi/lo W
// ---------------------------------------------------------------------------
__global__ __launch_bounds__(256) void mix_kernel(
    const float* __restrict__ wre, const float* __restrict__ wim)
{
    const int idx = blockIdx.x * 256 + threadIdx.x;       // Bd*64*36
    const int b = idx / (Cd * CAP);
    const int rem = idx - b * (Cd * CAP);
    const int c = rem / CAP, j = rem - c * CAP;
    const int m = g_rep_m[j];
    if (m < 0) return;

    float cr = 0.f, si = 0.f;
    const float* p = g_red + ((size_t)b * Cd + c) * 80;
    #pragma unroll
    for (int s = 0; s < 8; s++) {
        cr += p[(size_t)s * SLICE + j];
        si += p[(size_t)s * SLICE + 36 + j];
    }
    const float ci = -si, inv = 1.0f / (float)Nd;
    const float wr = wre[m * Cd + c], wi = wim[m * Cd + c];
    float A2 =  (cr * wr - ci * wi) * inv;
    float B2 = -(cr * wi + ci * wr) * inv;
    const int pp = g_rep_pair[j];
    if (pp >= 0) {
        const float wrp = wre[pp * Cd + c], wip = wim[pp * Cd + c];
        A2 += ( cr * wrp + ci * wip) * inv;
        B2 -= (-cr * wip + ci * wrp) * inv;
    }
    ush ah, al, bh, bl;
    splitb(A2, ah, al); splitb(B2, bh, bl);
    ush* W = g_W + ((size_t)b * Cd + c) * 160;
    W[j] = ah; W[36 + j] = bh; W[80 + j] = al; W[116 + j] = bl;
}

// ---------------------------------------------------------------------------
// K3 recon: D[n][c] = T[n][k] * W[c][k].  Block covers 256 n as TWO 128-n
// halves sharing one W tile (load + pad-zero amortized 2x).
// smem: Ts[128][168]h | Ws[64][168]h
// ---------------------------------------------------------------------------
#define RSTR 168
#define RSTRW 84
#define WS_OFF (128 * RSTR)
#define RECON_SMEM ((128 + 64) * RSTR * 2)

__global__ __launch_bounds__(256, 2) void recon_kernel(
    const float* __restrict__ coords, float* __restrict__ out)
{
    extern __shared__ __align__(16) ush sm[];
    ush* Ws = sm + WS_OFF;
    uint32_t* Twr = (uint32_t*)sm;
    uint32_t* Wwr = (uint32_t*)Ws;

    const int tid = threadIdx.x, wid = tid >> 5, lane = tid & 31;
    const int g = lane >> 2, tq = lane & 3;
    const int b = blockIdx.y, nblk = blockIdx.x * 256;

    // zero Ts pad words once: hi-pad 36..39 (halves 72..79) AND lo-pad
    // 76..79 (halves 152..159) — both read by the kstep loops, never
    // rewritten by the T build.
    if (tid < 128) {
        uint32_t* r = Twr + tid * RSTRW;
        r[36] = 0; r[37] = 0; r[38] = 0; r[39] = 0;
        r[76] = 0; r[77] = 0; r[78] = 0; r[79] = 0;
    }
    // W tile once: 64 rows x 20 uint4 (g_W pads are statically zero)
    for (int v = tid; v < 1280; v += 256) {
        const int c = v / 20, q2 = v - c * 20;
        const uint4 w = *(const uint4*)(g_W + ((size_t)b * Cd + c) * 160 + q2 * 8);
        *(uint4*)&Ws[c * RSTR + q2 * 8] = w;
    }

    const int nt = wid & 3;          // n32 tile: rows nt*32 .. +31
    const int ch = wid >> 2;         // c32 half: col tiles ch*4 .. ch*4+3

    #pragma unroll
    for (int half = 0; half < 2; half++) {
        const int n0 = nblk + half * 128;
        __syncthreads();             // W/pads ready (h0); prev MMA done (h1)

        // T tile: packed STS.32, jw-major: 128 n x 18 mode-pair words
        {
            const float2* cbase = ((const float2*)coords) + (size_t)b * Nd + n0;
            #pragma unroll
            for (int i = 0; i < 9; i++) {
                const int e = tid + 256 * i;              // 0..2303
                const int n = e / 18, jw = e - n * 18;
                const float2 cc = cbase[n];
                const int j0 = 2 * jw, j1 = j0 + 1;
                float s0, c0, s1, c1;
                trig_of2(cc.x, cc.y, g_rep_fx[j0], g_rep_fy[j0], s0, c0);
                trig_of2(cc.x, cc.y, g_rep_fx[j1], g_rep_fy[j1], s1, c1);
                uint32_t* r = Twr + n * RSTRW;
                r[jw]      = hi_pair(c0, c1);
                r[18 + jw] = hi_pair(s0, s1);
                r[40 + jw] = lo_pair(c0, c1);
                r[58 + jw] = lo_pair(s0, s1);
            }
        }
        __syncthreads();

        float acc[2][4][4];
        #pragma unroll
        for (int t = 0; t < 2; t++)
            #pragma unroll
            for (int u = 0; u < 4; u++)
                #pragma unroll
                for (int v = 0; v < 4; v++) acc[t][u][v] = 0.f;

        // 15 ksteps = 3 groups x 5; A (m32) shared across the 4 B tiles
        #pragma unroll
        for (int s = 0; s < 15; s++) {
            const int gr = s / 5, s5 = s - gr * 5;
            const int kwA = ((gr == 1) ? 40 : 0) + 8 * s5;   // T lo for group 1
            const int kwB = ((gr == 2) ? 40 : 0) + 8 * s5;   // W lo for group 2
            uint32_t a[2][4];
            #pragma unroll
            for (int tt = 0; tt < 2; tt++) {
                const int ra = (nt * 32 + tt * 16 + g) * RSTRW + kwA + tq;
                a[tt][0] = Twr[ra];             a[tt][1] = Twr[ra + 8 * RSTRW];
                a[tt][2] = Twr[ra + 4];         a[tt][3] = Twr[ra + 8 * RSTRW + 4];
            }
            #pragma unroll
            for (int u = 0; u < 4; u++) {
                uint32_t bb[2];
                const int rb = ((ch * 4 + u) * 8 + g) * RSTRW + kwB + tq;
                bb[0] = Wwr[rb]; bb[1] = Wwr[rb + 4];
                hmma(acc[0][u], a[0], bb);
                hmma(acc[1][u], a[1], bb);
            }
        }

        // epilogue: D[n][c] -> out
        #pragma unroll
        for (int tt = 0; tt < 2; tt++) {
            const int r0 = nt * 32 + tt * 16 + g;
            float* o0 = out + ((size_t)b * Nd + n0 + r0) * Cd;
            float* o1 = o0 + 8 * Cd;
            #pragma unroll
            for (int u = 0; u < 4; u++) {
                const int c = (ch * 4 + u) * 8 + 2 * tq;
                *(float2*)&o0[c] = make_float2(acc[tt][u][0], acc[tt][u][1]);
                *(float2*)&o1[c] = make_float2(acc[tt][u][2], acc[tt][u][3]);
            }
        }
    }
}

// ---------------------------------------------------------------------------
extern "C" void kernel_launch(void* const* d_in, const int* in_sizes, int n_in,
                              void* d_out, int out_size)
{
    const float* inputs = (const float*)d_in[0];
    const float* coords = (const float*)d_in[1];
    const float* wre    = (const float*)d_in[2];
    const float* wim    = (const float*)d_in[3];
    const float* freqs  = (const float*)d_in[4];
    float* out = (float*)d_out;

    cudaFuncSetAttribute(proj_kernel,  cudaFuncAttributeMaxDynamicSharedMemorySize, PROJ_SMEM);
    cudaFuncSetAttribute(recon_kernel, cudaFuncAttributeMaxDynamicSharedMemorySize, RECON_SMEM);

    setup_kernel<<<1, 64>>>(freqs);
    proj_kernel<<<dim3(Sp, Bd), 256, PROJ_SMEM>>>(inputs, coords);
    reduce_kernel<<<(8 * SLICE) / 256, 256>>>();
    mix_kernel<<<(Bd * Cd * CAP) / 256, 256>>>(wre, wim);
    recon_kernel<<<dim3(Nd / 256, Bd), 256, RECON_SMEM>>>(coords, out);
}

// round 17
// speedup vs baseline: 1.0244x; 1.0224x over previous
#include <cuda_runtime.h>
#include <cuda_bf16.h>
#include <cstdint>

#define Bd 8
#define Nd 65536
#define Cd 64
#define Md 64
#define CAP 36
#define Sp 256            // proj splits per batch (4 chunks of 64 n each)
#define PCHUNKS ((Nd / Sp) / 64)
#define SLICE (Bd * Cd * 80)
#define TWOPI 6.283185307179586f

typedef unsigned short ush;

// ---------------- device scratch (no allocation; statically zeroed) --------
__device__ float g_rep_fx[CAP], g_rep_fy[CAP];
__device__ int   g_rep_m[CAP], g_rep_pair[CAP];
__device__ float g_partial[(size_t)Sp * SLICE];          // [split][b][c][80]
__device__ float g_red[(size_t)8 * SLICE];               // [8][b][c][80]
__device__ ush   g_W[(size_t)Bd * Cd * 160];             // [b][c][160]; pads stay 0

// ---------------- helpers ----------------
__device__ __forceinline__ void splitb(float x, ush& h, ush& l) {
    uint32_t u = __float_as_uint(x);
    h = (ush)(u >> 16);                                   // truncation (exact hi)
    __nv_bfloat16 lb = __float2bfloat16(x - __uint_as_float(u & 0xFFFF0000u));
    l = *reinterpret_cast<ush*>(&lb);
}
// hi word of pair: {lo16: trunc16(f0), hi16: trunc16(f1)}
__device__ __forceinline__ uint32_t hi_pair(float f0, float f1) {
    uint32_t r;
    asm("prmt.b32 %0, %1, %2, 0x7632;" : "=r"(r)
        : "r"(__float_as_uint(f0)), "r"(__float_as_uint(f1)));
    return r;
}
// lo word of pair: {lo16: bf16(f0-hi0), hi16: bf16(f1-hi1)}
__device__ __forceinline__ uint32_t lo_pair(float f0, float f1) {
    float l0 = f0 - __uint_as_float(__float_as_uint(f0) & 0xFFFF0000u);
    float l1 = f1 - __uint_as_float(__float_as_uint(f1) & 0xFFFF0000u);
    uint32_t r;
    asm("cvt.rn.bf16x2.f32 %0, %1, %2;" : "=r"(r) : "f"(l1), "f"(l0));
    return r;
}
__device__ __forceinline__ void trig_of2(float cx, float cy, float fx, float fy,
                                         float& s, float& c) {
    float t = cx * fx + cy * fy;                          // integer freqs
    float ph = TWOPI * (t - rintf(t));                    // exact reduce to [-pi,pi]
    __sincosf(ph, &s, &c);
}
// D(16x8,f32) += A(16x16 row,bf16) * B(16x8 col,bf16)
__device__ __forceinline__ void hmma(float* d, const uint32_t* a, const uint32_t* b) {
    asm volatile(
        "mma.sync.aligned.m16n8k16.row.col.f32.bf16.bf16.f32 "
        "{%0,%1,%2,%3},{%4,%5,%6,%7},{%8,%9},{%0,%1,%2,%3};"
        : "+f"(d[0]), "+f"(d[1]), "+f"(d[2]), "+f"(d[3])
        : "r"(a[0]), "r"(a[1]), "r"(a[2]), "r"(a[3]), "r"(b[0]), "r"(b[1]));
}

// ---------------------------------------------------------------------------
// K0: conjugate-pair discovery (parallel; deterministic rep order)
// ---------------------------------------------------------------------------
__global__ void setup_kernel(const float* __restrict__ freqs) {
    __shared__ float sfx[Md], sfy[Md];
    __shared__ int sp[Md];
    const int m = threadIdx.x;                 // 64 threads
    const float fx = freqs[2 * m], fy = freqs[2 * m + 1];
    sfx[m] = fx; sfy[m] = fy;
    __syncthreads();
    int p = -1;
    for (int q = 0; q < Md; q++)
        if (q != m && sfx[q] == -fx && sfy[q] == -fy) { p = q; break; }
    sp[m] = p;
    __syncthreads();
    if (m == 0) {
        int cnt = 0;
        for (int mm = 0; mm < Md && cnt < CAP; mm++) {
            const int pp = sp[mm];
            if (pp >= 0 && pp < mm) continue;  // covered by an earlier rep
            g_rep_m[cnt] = mm; g_rep_pair[cnt] = pp;
            g_rep_fx[cnt] = sfx[mm]; g_rep_fy[cnt] = sfy[mm]; cnt++;
        }
        for (int j = cnt; j < CAP; j++) {
            g_rep_m[j] = -1; g_rep_pair[j] = -1;
            g_rep_fx[j] = 0.f; g_rep_fy[j] = 0.f;
        }
    }
}

// ---------------------------------------------------------------------------
// K1 proj: D[c(64)][j2(80)] += X[c][k] * T[j2][k] over n, bf16 hi/lo.
// Software-pipelined: X gmem loads for chunk t+1 issue before the MMA loop
// of chunk t (registers carry them across the barrier); conversion + STS
// happen at the top of the next iteration.
// smem: Xw[64 c][68 words] | Tw[80 j2][68 words]   (hi words 0-31, lo 32-63)
// ---------------------------------------------------------------------------
#define PSTRW 68
#define PROJ_SMEM ((64 + 80) * PSTRW * 4)

__global__ __launch_bounds__(256, 3) void proj_kernel(
    const float* __restrict__ inputs, const float* __restrict__ coords)
{
    extern __shared__ __align__(16) uint32_t smw[];
    uint32_t* Xw = smw;                        // [64][68]
    uint32_t* Tw = smw + 64 * PSTRW;           // [80][68]

    const int tid = threadIdx.x, wid = tid >> 5, lane = tid & 31;
    const int g = lane >> 2, tq = lane & 3;
    const int split = blockIdx.x, b = blockIdx.y;

    // zero T pad rows 72-79 once (read by MMA, never written)
    for (int i = tid; i < 8 * PSTRW; i += 256) Tw[72 * PSTRW + i] = 0;

    const int mt = wid >> 1;                   // c tile: c0 = mt*16
    const int nb = (wid & 1) * 5;              // j2 tiles nb..nb+4

    float acc[5][4];
    #pragma unroll
    for (int u = 0; u < 5; u++)
        #pragma unroll
        for (int v = 0; v < 4; v++) acc[u][v] = 0.f;

    const int nbase = split * (Nd / Sp);
    const int npl = 4 * wid + tq;              // this lane's n-pair (0..31)
    const float* xbase = inputs + (size_t)b * Nd * Cd;
    const int r0 = 2 * npl;

    float xf[16];
    // preload chunk 0
    {
        const float* xrow = xbase + (size_t)nbase * Cd;
        #pragma unroll
        for (int ic = 0; ic < 8; ic++) {
            const int c = g + 8 * ic;
            xf[2 * ic]     = xrow[(size_t)r0 * Cd + c];
            xf[2 * ic + 1] = xrow[(size_t)(r0 + 1) * Cd + c];
        }
    }

    for (int t = 0; t < PCHUNKS; t++) {
        const int n0 = nbase + t * 64;
        __syncthreads();                       // tiles free (prev MMA done)

        // ---- X build from prefetched registers: pairwise bf16 -> CF STS ----
        #pragma unroll
        for (int ic = 0; ic < 8; ic++) {
            const int c = g + 8 * ic;
            Xw[c * PSTRW + npl]      = hi_pair(xf[2 * ic], xf[2 * ic + 1]);
            Xw[c * PSTRW + 32 + npl] = lo_pair(xf[2 * ic], xf[2 * ic + 1]);
        }
        // ---- T build: 1152 (j, n-pair) items, pairwise conversion ----
        {
            const float* cbase = coords + ((size_t)b * Nd + n0) * 2;
            for (int e = tid; e < 1152; e += 256) {
                const int j = e >> 5, w = e & 31;
                const float4 cc = *(const float4*)(cbase + 4 * w);
                const float fx = g_rep_fx[j], fy = g_rep_fy[j];
                float s0, c0, s1, c1;
                trig_of2(cc.x, cc.y, fx, fy, s0, c0);
                trig_of2(cc.z, cc.w, fx, fy, s1, c1);
                uint32_t* r = Tw + j * PSTRW;
                r[w]      = hi_pair(c0, c1);
                r[32 + w] = lo_pair(c0, c1);
                r += 36 * PSTRW;
                r[w]      = hi_pair(s0, s1);
                r[32 + w] = lo_pair(s0, s1);
            }
        }
        __syncthreads();

        // ---- prefetch chunk t+1 (overlaps the MMA loop below) ----
        if (t + 1 < PCHUNKS) {
            const float* xrow = xbase + (size_t)(n0 + 64) * Cd;
            #pragma unroll
            for (int ic = 0; ic < 8; ic++) {
                const int c = g + 8 * ic;
                xf[2 * ic]     = xrow[(size_t)r0 * Cd + c];
                xf[2 * ic + 1] = xrow[(size_t)(r0 + 1) * Cd + c];
            }
        }

        // ---- MMA: 12 ksteps = 3 product groups x 4 ----
        #pragma unroll
        for (int gr = 0; gr < 3; gr++) {
            const int kwAb = (gr == 1) ? 32 : 0;     // X lo for group 1
            const int kwBb = (gr == 2) ? 32 : 0;     // T lo for group 2
            #pragma unroll
            for (int s = 0; s < 4; s++) {
                const int kwA = kwAb + 8 * s, kwB = kwBb + 8 * s;
                uint32_t a[4];
                const int ra = (mt * 16 + g) * PSTRW + kwA + tq;
                a[0] = Xw[ra];              a[1] = Xw[ra + 8 * PSTRW];
                a[2] = Xw[ra + 4];          a[3] = Xw[ra + 8 * PSTRW + 4];
                #pragma unroll
                for (int u = 0; u < 5; u++) {
                    uint32_t bb[2];
                    const int rb = ((nb + u) * 8 + g) * PSTRW + kwB + tq;
                    bb[0] = Tw[rb]; bb[1] = Tw[rb + 4];
                    hmma(acc[u], a, bb);
                }
            }
        }
    }

    // epilogue: D[c][j2] -> g_partial[split][b][c][80]
    float* dst = g_partial + (((size_t)split * Bd + b) * Cd) * 80;
    #pragma unroll
    for (int u = 0; u < 5; u++) {
        const int j = (nb + u) * 8 + 2 * tq;
        const int c0 = mt * 16 + g;
        *(float2*)&dst[(size_t)c0 * 80 + j]       = make_float2(acc[u][0], acc[u][1]);
        *(float2*)&dst[(size_t)(c0 + 8) * 80 + j] = make_float2(acc[u][2], acc[u][3]);
    }
}

// ---------------------------------------------------------------------------
// K2a: parallel reduce Sp slices -> 8 (coalesced; deterministic grouping)
// ---------------------------------------------------------------------------
__global__ __launch_bounds__(256) void reduce_kernel() {
    const int idx = blockIdx.x * 256 + threadIdx.x;       // over 8*SLICE
    const int r8 = idx / SLICE;
    const int rem = idx - r8 * SLICE;
    const float* p = g_partial + (size_t)r8 * (Sp / 8) * SLICE + rem;
    float s = 0.f;
    #pragma unroll 8
    for (int i = 0; i < Sp / 8; i++) s += p[(size_t)i * SLICE];
    g_red[idx] = s;
}

// ---------------------------------------------------------------------------
// K2b mix: reduce 8 slices, 1/N + weight + conj fold, emit bf16 hi/lo W
// ---------------------------------------------------------------------------
__global__ __launch_bounds__(256) void mix_kernel(
    const float* __restrict__ wre, const float* __restrict__ wim)
{
    const int idx = blockIdx.x * 256 + threadIdx.x;       // Bd*64*36
    const int b = idx / (Cd * CAP);
    const int rem = idx - b * (Cd * CAP);
    const int c = rem / CAP, j = rem - c * CAP;
    const int m = g_rep_m[j];
    if (m < 0) return;

    float cr = 0.f, si = 0.f;
    const float* p = g_red + ((size_t)b * Cd + c) * 80;
    #pragma unroll
    for (int s = 0; s < 8; s++) {
        cr += p[(size_t)s * SLICE + j];
        si += p[(size_t)s * SLICE + 36 + j];
    }
    const float ci = -si, inv = 1.0f / (float)Nd;
    const float wr = wre[m * Cd + c], wi = wim[m * Cd + c];
    float A2 =  (cr * wr - ci * wi) * inv;
    float B2 = -(cr * wi + ci * wr) * inv;
    const int pp = g_rep_pair[j];
    if (pp >= 0) {
        const float wrp = wre[pp * Cd + c], wip = wim[pp * Cd + c];
        A2 += ( cr * wrp + ci * wip) * inv;
        B2 -= (-cr * wip + ci * wrp) * inv;
    }
    ush ah, al, bh, bl;
    splitb(A2, ah, al); splitb(B2, bh, bl);
    ush* W = g_W + ((size_t)b * Cd + c) * 160;
    W[j] = ah; W[36 + j] = bh; W[80 + j] = al; W[116 + j] = bl;
}

// ---------------------------------------------------------------------------
// K3 recon: D[n(128)][c(64)] = T[n][k] * W[c][k]   (exact R13 structure)
// warp = (n32-tile, c32-half): m32n32 per warp, A-frags shared across halves
// smem: Ts[128][168]h | Ws[64][168]h
// ---------------------------------------------------------------------------
#define RSTR 168
#define RSTRW 84
#define WS_OFF (128 * RSTR)
#define RECON_SMEM ((128 + 64) * RSTR * 2)

__global__ __launch_bounds__(256, 2) void recon_kernel(
    const float* __restrict__ coords, float* __restrict__ out)
{
    extern __shared__ __align__(16) ush sm[];
    ush* Ws = sm + WS_OFF;
    uint32_t* Twr = (uint32_t*)sm;
    uint32_t* Wwr = (uint32_t*)Ws;

    const int tid = threadIdx.x, wid = tid >> 5, lane = tid & 31;
    const int g = lane >> 2, tq = lane & 3;
    const int b = blockIdx.y, n0 = blockIdx.x * 128;

    // zero Ts pad words: hi-pad 36..39 (halves 72..79) AND lo-pad 76..79
    // (halves 152..159) — both are read by the kstep loops.
    if (tid < 128) {
        uint32_t* r = Twr + tid * RSTRW;
        r[36] = 0; r[37] = 0; r[38] = 0; r[39] = 0;
        r[76] = 0; r[77] = 0; r[78] = 0; r[79] = 0;
    }
    // W tile: 64 rows x 20 uint4 (g_W pads are statically zero)
    for (int v = tid; v < 1280; v += 256) {
        const int c = v / 20, q2 = v - c * 20;
        const uint4 w = *(const uint4*)(g_W + ((size_t)b * Cd + c) * 160 + q2 * 8);
        *(uint4*)&Ws[c * RSTR + q2 * 8] = w;
    }
    // T tile: packed STS.32, jw-major: 128 n x 18 mode-pair words
    {
        const float2* cbase = ((const float2*)coords) + (size_t)b * Nd + n0;
        #pragma unroll
        for (int i = 0; i < 9; i++) {
            const int e = tid + 256 * i;              // 0..2303
            const int n = e / 18, jw = e - n * 18;
            const float2 cc = cbase[n];
            const int j0 = 2 * jw, j1 = j0 + 1;
            float s0, c0, s1, c1;
            trig_of2(cc.x, cc.y, g_rep_fx[j0], g_rep_fy[j0], s0, c0);
            trig_of2(cc.x, cc.y, g_rep_fx[j1], g_rep_fy[j1], s1, c1);
            uint32_t* r = Twr + n * RSTRW;
            r[jw]      = hi_pair(c0, c1);
            r[18 + jw] = hi_pair(s0, s1);
            r[40 + jw] = lo_pair(c0, c1);
            r[58 + jw] = lo_pair(s0, s1);
        }
    }
    __syncthreads();

    const int nt = wid & 3;          // n32 tile: rows nt*32 .. +31
    const int ch = wid >> 2;         // c32 half: col tiles ch*4 .. ch*4+3

    float acc[2][4][4];
    #pragma unroll
    for (int t = 0; t < 2; t++)
        #pragma unroll
        for (int u = 0; u < 4; u++)
            #pragma unroll
            for (int v = 0; v < 4; v++) acc[t][u][v] = 0.f;

    // 15 ksteps = 3 groups x 5; A (m32) shared across the 4 B tiles
    #pragma unroll
    for (int s = 0; s < 15; s++) {
        const int gr = s / 5, s5 = s - gr * 5;
        const int kwA = ((gr == 1) ? 40 : 0) + 8 * s5;   // T lo for group 1
        const int kwB = ((gr == 2) ? 40 : 0) + 8 * s5;   // W lo for group 2
        uint32_t a[2][4];
        #pragma unroll
        for (int tt = 0; tt < 2; tt++) {
            const int ra = (nt * 32 + tt * 16 + g) * RSTRW + kwA + tq;
            a[tt][0] = Twr[ra];             a[tt][1] = Twr[ra + 8 * RSTRW];
            a[tt][2] = Twr[ra + 4];         a[tt][3] = Twr[ra + 8 * RSTRW + 4];
        }
        #pragma unroll
        for (int u = 0; u < 4; u++) {
            uint32_t bb[2];
            const int rb = ((ch * 4 + u) * 8 + g) * RSTRW + kwB + tq;
            bb[0] = Wwr[rb]; bb[1] = Wwr[rb + 4];
            hmma(acc[0][u], a[0], bb);
            hmma(acc[1][u], a[1], bb);
        }
    }

    // epilogue: D[n][c] -> out
    #pragma unroll
    for (int tt = 0; tt < 2; tt++) {
        const int r0 = nt * 32 + tt * 16 + g;
        float* o0 = out + ((size_t)b * Nd + n0 + r0) * Cd;
        float* o1 = o0 + 8 * Cd;
        #pragma unroll
        for (int u = 0; u < 4; u++) {
            const int c = (ch * 4 + u) * 8 + 2 * tq;
            *(float2*)&o0[c] = make_float2(acc[tt][u][0], acc[tt][u][1]);
            *(float2*)&o1[c] = make_float2(acc[tt][u][2], acc[tt][u][3]);
        }
    }
}

// ---------------------------------------------------------------------------
extern "C" void kernel_launch(void* const* d_in, const int* in_sizes, int n_in,
                              void* d_out, int out_size)
{
    const float* inputs = (const float*)d_in[0];
    const float* coords = (const float*)d_in[1];
    const float* wre    = (const float*)d_in[2];
    const float* wim    = (const float*)d_in[3];
    const float* freqs  = (const float*)d_in[4];
    float* out = (float*)d_out;

    cudaFuncSetAttribute(proj_kernel,  cudaFuncAttributeMaxDynamicSharedMemorySize, PROJ_SMEM);
    cudaFuncSetAttribute(recon_kernel, cudaFuncAttributeMaxDynamicSharedMemorySize, RECON_SMEM);

    setup_kernel<<<1, 64>>>(freqs);
    proj_kernel<<<dim3(Sp, Bd), 256, PROJ_SMEM>>>(inputs, coords);
    reduce_kernel<<<(8 * SLICE) / 256, 256>>>();
    mix_kernel<<<(Bd * Cd * CAP) / 256, 256>>>(wre, wim);
    recon_kernel<<<dim3(Nd / 128, Bd), 256, RECON_SMEM>>>(coords, out);
}